// round 5
// baseline (speedup 1.0000x reference)
#include <cuda_runtime.h>
#include <cuda_bf16.h>
#include <math.h>
#include <stddef.h>
#include <stdint.h>

#define BB 8
#define LL 2048
#define NNV 512
#define HHV 16
#define CCV 16
#define DDV 64
#define TKV 45
#define BLV (BB*LL)
#define KE2 544   // 512 + 16 (rank-16 fold) + 16 zero pad -> 17 stages of 32

__device__ __forceinline__ void bfsplit(float v, __nv_bfloat16& h, __nv_bfloat16& l) {
    h = __float2bfloat16(v);
    l = __float2bfloat16(v - __bfloat162float(h));
}

__device__ __forceinline__ void mma16816(float& c0, float& c1, float& c2, float& c3,
                                         uint32_t a0, uint32_t a1, uint32_t a2, uint32_t a3,
                                         uint32_t b0, uint32_t b1) {
    asm volatile(
        "mma.sync.aligned.m16n8k16.row.col.f32.bf16.bf16.f32 "
        "{%0,%1,%2,%3}, {%4,%5,%6,%7}, {%8,%9}, {%0,%1,%2,%3};"
        : "+f"(c0), "+f"(c1), "+f"(c2), "+f"(c3)
        : "r"(a0), "r"(a1), "r"(a2), "r"(a3), "r"(b0), "r"(b1));
}

__device__ __forceinline__ uint32_t smem_u32(const void* p) {
    uint32_t a;
    asm("{ .reg .u64 t; cvta.to.shared.u64 t, %1; cvt.u32.u64 %0, t; }" : "=r"(a) : "l"(p));
    return a;
}
__device__ __forceinline__ void cp16(uint32_t dst, const void* src) {
    asm volatile("cp.async.cg.shared.global [%0], [%1], 16;" :: "r"(dst), "l"(src));
}

// ===================== scratch (device globals) =====================
__device__ float g_simpart[8*NNV*NNV];
__device__ float g_sim[NNV*NNV];
__device__ int   g_topk[NNV*TKV];
__device__ float g_attn[BB*NNV*TKV];
__device__ float g_Q[BB*NNV*HHV];
__device__ float g_K[BB*NNV*HHV];
__device__ float g_imp[BB*NNV];
__device__ float g_summary[BB*NNV];
__device__ float g_ps[BB*16*NNV];
__device__ float g_pq[BB*16*NNV];
__device__ float g_cw[NNV*CCV];
__device__ float g_cwT[CCV*NNV];
__device__ float g_M1[CCV*DDV];
__device__ float g_bb[DDV];
__device__ float g_w2[DDV];
__device__ float g_b2s;
__device__ float g_ct[BB*CCV*DDV];
__device__ float g_ctp[BB*CCV*DDV];
__device__ float g_xcs[(size_t)BLV*CCV];
__device__ float g_ring[(size_t)BLV*NNV];
__device__ float g_c2v[(size_t)BLV*NNV];
__device__ float g_h[(size_t)BLV*NNV];
__device__ __align__(16) __nv_bfloat16 g_nTh[NNV*LL];
__device__ __align__(16) __nv_bfloat16 g_nTl[NNV*LL];
__device__ __align__(16) __nv_bfloat16 g_A1h[(size_t)BLV*KE2];
__device__ __align__(16) __nv_bfloat16 g_A1l[(size_t)BLV*KE2];
__device__ __align__(16) __nv_bfloat16 g_A2h[(size_t)BLV*KE2];
__device__ __align__(16) __nv_bfloat16 g_A2l[(size_t)BLV*KE2];
__device__ __align__(16) __nv_bfloat16 g_B1h[NNV*KE2];
__device__ __align__(16) __nv_bfloat16 g_B1l[NNV*KE2];
__device__ __align__(16) __nv_bfloat16 g_B2h[NNV*KE2];
__device__ __align__(16) __nv_bfloat16 g_B2l[NNV*KE2];

// ===================== 1. column stats over batch -> normedT hi/lo ==========
__global__ void k_colstats(const float* __restrict__ x) {
    int i = blockIdx.x * 256 + threadIdx.x;
    if (i >= LL*NNV) return;
    float v[BB];
#pragma unroll
    for (int b = 0; b < BB; b++) v[b] = x[(size_t)b*LL*NNV + i];
    float s = 0.f;
#pragma unroll
    for (int b = 0; b < BB; b++) s += v[b];
    float mean = s * (1.0f/BB);
    float q = 0.f;
#pragma unroll
    for (int b = 0; b < BB; b++) { float d = v[b]-mean; q += d*d; }
    float stdv = sqrtf(q * (1.0f/(BB-1))) + 1e-5f;
    float nv = mean / stdv;
    int n = i & 511, l = i >> 9;
    __nv_bfloat16 h, lo;
    bfsplit(nv, h, lo);
    g_nTh[(size_t)n*LL + l] = h;
    g_nTl[(size_t)n*LL + l] = lo;
}

// ===================== unified pipelined 3-pass bf16 HMMA GEMM ==============
// CTA tile 128x128, 8 warps (2 warpM x 4 warpN), warp tile 64x32.
// smem: double buffer; each buffer: AH[128][40] AL BH[128][40] BL (bf16).
// EP0: sim split-K partial (fp32 out). EP1: gate epilogue. EP2: fuse epilogue.
#define GPAD 40
#define BUFE (128*GPAD)          // elems per array
#define BUFSTRIDE (4*BUFE)       // elems per buffer (4 arrays)

template<int EP>
__global__ void __launch_bounds__(256) k_gmma(
    const __nv_bfloat16* __restrict__ Ah, const __nv_bfloat16* __restrict__ Al, int lda,
    const __nv_bfloat16* __restrict__ Bh, const __nv_bfloat16* __restrict__ Bl, int ldb,
    int kz, int nStages,
    const float* __restrict__ bias,
    const float* __restrict__ e0, const float* __restrict__ e1,
    __nv_bfloat16* __restrict__ o0, __nv_bfloat16* __restrict__ o1,
    float* __restrict__ outF)
{
    extern __shared__ __align__(16) __nv_bfloat16 sm[];
    const uint32_t smb = smem_u32(sm);
    int tid = threadIdx.x;
    int wid = tid >> 5, lane = tid & 31;
    int gr = lane >> 2, tc = lane & 3;
    int warpM = wid >> 2, warpN = wid & 3;
    int row0 = blockIdx.y * 128, col0 = blockIdx.x * 128;
    int kStart = blockIdx.z * kz;

    float acc[4][4][4];
#pragma unroll
    for (int mt = 0; mt < 4; mt++)
#pragma unroll
        for (int nt = 0; nt < 4; nt++)
#pragma unroll
            for (int i = 0; i < 4; i++) acc[mt][nt][i] = 0.f;

#define LOAD_STAGE(S) do { \
    int _buf = (S) & 1; \
    int _k0 = kStart + (S)*32; \
    uint32_t _sb = smb + _buf*(BUFSTRIDE*2); \
    _Pragma("unroll") \
    for (int _j = 0; _j < 2; _j++) { \
        int _idx = tid + _j*256; \
        int _r = _idx >> 2, _c = _idx & 3; \
        uint32_t _do = (uint32_t)(_r*GPAD + _c*8)*2; \
        cp16(_sb + _do,             Ah + (size_t)(row0+_r)*lda + _k0 + _c*8); \
        cp16(_sb + BUFE*2 + _do,    Al + (size_t)(row0+_r)*lda + _k0 + _c*8); \
        cp16(_sb + 2*BUFE*2 + _do,  Bh + (size_t)(col0+_r)*ldb + _k0 + _c*8); \
        cp16(_sb + 3*BUFE*2 + _do,  Bl + (size_t)(col0+_r)*ldb + _k0 + _c*8); \
    } } while (0)

    LOAD_STAGE(0);
    asm volatile("cp.async.commit_group;");

    for (int s = 0; s < nStages; s++) {
        if (s + 1 < nStages) LOAD_STAGE(s + 1);
        asm volatile("cp.async.commit_group;");
        asm volatile("cp.async.wait_group 1;");
        __syncthreads();
        const __nv_bfloat16* sAh = sm + (s & 1)*BUFSTRIDE;
        const __nv_bfloat16* sAl = sAh + BUFE;
        const __nv_bfloat16* sBh = sAh + 2*BUFE;
        const __nv_bfloat16* sBl = sAh + 3*BUFE;
#pragma unroll
        for (int kk = 0; kk < 2; kk++) {
            int ko = kk*16 + tc*2;
            uint32_t aH[4][4], aL[4][4];
#pragma unroll
            for (int mt = 0; mt < 4; mt++) {
                int R = (warpM*64 + mt*16 + gr)*GPAD + ko;
                aH[mt][0] = *(const uint32_t*)(sAh + R);
                aH[mt][1] = *(const uint32_t*)(sAh + R + 8*GPAD);
                aH[mt][2] = *(const uint32_t*)(sAh + R + 8);
                aH[mt][3] = *(const uint32_t*)(sAh + R + 8*GPAD + 8);
                aL[mt][0] = *(const uint32_t*)(sAl + R);
                aL[mt][1] = *(const uint32_t*)(sAl + R + 8*GPAD);
                aL[mt][2] = *(const uint32_t*)(sAl + R + 8);
                aL[mt][3] = *(const uint32_t*)(sAl + R + 8*GPAD + 8);
            }
            uint32_t bH[4][2], bL[4][2];
#pragma unroll
            for (int nt = 0; nt < 4; nt++) {
                int R = (warpN*32 + nt*8 + gr)*GPAD + ko;
                bH[nt][0] = *(const uint32_t*)(sBh + R);
                bH[nt][1] = *(const uint32_t*)(sBh + R + 8);
                bL[nt][0] = *(const uint32_t*)(sBl + R);
                bL[nt][1] = *(const uint32_t*)(sBl + R + 8);
            }
#pragma unroll
            for (int mt = 0; mt < 4; mt++)
#pragma unroll
                for (int nt = 0; nt < 4; nt++) {
                    float* c = acc[mt][nt];
                    mma16816(c[0],c[1],c[2],c[3], aH[mt][0],aH[mt][1],aH[mt][2],aH[mt][3], bH[nt][0],bH[nt][1]);
                    mma16816(c[0],c[1],c[2],c[3], aH[mt][0],aH[mt][1],aH[mt][2],aH[mt][3], bL[nt][0],bL[nt][1]);
                    mma16816(c[0],c[1],c[2],c[3], aL[mt][0],aL[mt][1],aL[mt][2],aL[mt][3], bH[nt][0],bH[nt][1]);
                }
        }
        __syncthreads();
    }
#undef LOAD_STAGE

    // ---- epilogue ----
    size_t zoff = (EP == 0) ? (size_t)blockIdx.z * NNV * NNV : 0;
#pragma unroll
    for (int mt = 0; mt < 4; mt++) {
#pragma unroll
        for (int half = 0; half < 2; half++) {
            int row = row0 + warpM*64 + mt*16 + gr + half*8;
#pragma unroll
            for (int nt = 0; nt < 4; nt++) {
                int col = col0 + warpN*32 + nt*8 + tc*2;
                float c0 = acc[mt][nt][half*2 + 0];
                float c1 = acc[mt][nt][half*2 + 1];
                size_t ro = (size_t)row*512 + col;
                if (EP == 0) {
                    float2 ov; ov.x = c0; ov.y = c1;
                    *(float2*)(outF + zoff + ro) = ov;
                } else if (EP == 1) {
                    float2 bs = *(const float2*)(bias + col);
                    float2 rg = *(const float2*)(e0 + ro);
                    float2 cv = *(const float2*)(e1 + ro);
                    float g0 = 1.f/(1.f + __expf(-(c0 + bs.x)));
                    float g1 = 1.f/(1.f + __expf(-(c1 + bs.y)));
                    float t0 = g0*(rg.x - cv.x);
                    float t1 = g1*(rg.y - cv.y);
                    __nv_bfloat16 h0, l0, h1, l1;
                    bfsplit(t0, h0, l0); bfsplit(t1, h1, l1);
                    size_t ro6 = (size_t)row*KE2 + col;
                    __nv_bfloat162 hh; hh.x = h0; hh.y = h1;
                    __nv_bfloat162 llv; llv.x = l0; llv.y = l1;
                    *(__nv_bfloat162*)(o0 + ro6) = hh;
                    *(__nv_bfloat162*)(o1 + ro6) = llv;
                } else {
                    float2 bs = *(const float2*)(bias + col);
                    float2 xv = *(const float2*)(e0 + ro);
                    float2 hv;
                    hv.x = c0 + bs.x + xv.x;
                    hv.y = c1 + bs.y + xv.y;
                    *(float2*)(outF + ro) = hv;
                }
            }
        }
    }
}

// ===================== sim reduce =====================
__global__ void k_simred() {
    int i = blockIdx.x*256 + threadIdx.x;
    if (i >= NNV*NNV) return;
    float s = 0.f;
#pragma unroll
    for (int z = 0; z < 8; z++) s += g_simpart[(size_t)z*NNV*NNV + i];
    g_sim[i] = s;
}

// ===================== top-45 per row (warp per row) =====================
__global__ void k_topk() {
    int warp = threadIdx.x >> 5, lane = threadIdx.x & 31;
    int n = blockIdx.x*4 + warp;
    float v[16];
#pragma unroll
    for (int j = 0; j < 16; j++) {
        int col = j*32 + lane;
        v[j] = (col == n) ? -3.0e38f : g_sim[(size_t)n*NNV + col];
    }
    float lm = -3.0e38f; int li = 0;
#pragma unroll
    for (int j = 0; j < 16; j++) if (v[j] > lm) { lm = v[j]; li = j; }
    for (int it = 0; it < TKV; it++) {
        float m = lm; int src = lane;
#pragma unroll
        for (int o = 16; o; o >>= 1) {
            float om = __shfl_xor_sync(0xffffffffu, m, o);
            int os = __shfl_xor_sync(0xffffffffu, src, o);
            if (om > m || (om == m && os < src)) { m = om; src = os; }
        }
        int wli = __shfl_sync(0xffffffffu, li, src);
        if (lane == 0) g_topk[n*TKV + it] = wli*32 + src;
        if (lane == src) {
#pragma unroll
            for (int j = 0; j < 16; j++) if (j == li) v[j] = -3.0e38f;
            lm = -3.0e38f; li = 0;
#pragma unroll
            for (int j = 0; j < 16; j++) if (v[j] > lm) { lm = v[j]; li = j; }
        }
    }
}

// ===================== per-(b,n) partial sums over L =====================
__global__ void k_partsums(const float* __restrict__ x) {
    int b = blockIdx.x >> 4, ch = blockIdx.x & 15;
    for (int n = threadIdx.x; n < NNV; n += 256) {
        float s = 0.f, q = 0.f;
        const float* p = x + ((size_t)b*LL + ch*128)*NNV + n;
        for (int l = 0; l < 128; l++) { float v = p[(size_t)l*NNV]; s += v; q += v*v; }
        g_ps[(size_t)blockIdx.x*NNV + n] = s;
        g_pq[(size_t)blockIdx.x*NNV + n] = q;
    }
}

// ===================== router head =====================
__global__ void k_router(const float* __restrict__ var_embed,
                         const float* __restrict__ temp_w, const float* __restrict__ temp_b,
                         const float* __restrict__ q_w, const float* __restrict__ q_b,
                         const float* __restrict__ k_w, const float* __restrict__ k_b,
                         const float* __restrict__ imp_w, const float* __restrict__ imp_b) {
    int idx = blockIdx.x*256 + threadIdx.x;
    if (idx >= BB*NNV) return;
    int n = idx & (NNV-1);
    int b = idx >> 9;
    float s = 0.f, q = 0.f;
#pragma unroll
    for (int ch = 0; ch < 16; ch++) {
        s += g_ps[(size_t)(b*16+ch)*NNV + n];
        q += g_pq[(size_t)(b*16+ch)*NNV + n];
    }
    float mean = s * (1.0f/LL);
    float var  = (q - s*mean) * (1.0f/(LL-1));
    float stdv = sqrtf(var + 1e-5f);
    g_summary[idx] = mean;

    float vf[32];
#pragma unroll
    for (int h = 0; h < 16; h++) vf[h] = var_embed[n*16 + h];
#pragma unroll
    for (int h = 0; h < 16; h++) vf[16+h] = mean*temp_w[h] + stdv*temp_w[16+h] + temp_b[h];

    float ip = imp_b[0];
#pragma unroll
    for (int j = 0; j < 32; j++) ip += vf[j]*imp_w[j];
    g_imp[idx] = 1.f/(1.f + expf(-ip));

#pragma unroll
    for (int h = 0; h < 16; h++) {
        float qa = q_b[h], ka = k_b[h];
#pragma unroll
        for (int j = 0; j < 32; j++) { qa += vf[j]*q_w[j*16+h]; ka += vf[j]*k_w[j*16+h]; }
        g_Q[(size_t)idx*16 + h] = qa;
        g_K[(size_t)idx*16 + h] = ka;
    }
}

// ===================== sparse attention softmax =====================
__global__ void k_attn() {
    int w = threadIdx.x >> 5, lane = threadIdx.x & 31;
    int id = blockIdx.x*8 + w;
    int n = id & 511;
    int b = id >> 9;
    float qv[16];
#pragma unroll
    for (int h = 0; h < 16; h++) qv[h] = g_Q[(size_t)id*16 + h];
    int m1 = g_topk[n*TKV + lane];
    float s1 = 0.f;
#pragma unroll
    for (int h = 0; h < 16; h++) s1 += qv[h]*g_K[((size_t)b*512+m1)*16 + h];
    s1 *= 0.25f;
    float s2 = -3.0e38f;
    if (lane < TKV-32) {
        int m2 = g_topk[n*TKV + 32 + lane];
        float t = 0.f;
#pragma unroll
        for (int h = 0; h < 16; h++) t += qv[h]*g_K[((size_t)b*512+m2)*16 + h];
        s2 = t * 0.25f;
    }
    float mx = fmaxf(s1, s2);
#pragma unroll
    for (int o = 16; o; o >>= 1) mx = fmaxf(mx, __shfl_xor_sync(0xffffffffu, mx, o));
    float e1 = expf(s1 - mx);
    float e2 = (lane < TKV-32) ? expf(s2 - mx) : 0.f;
    float sm = e1 + e2;
#pragma unroll
    for (int o = 16; o; o >>= 1) sm += __shfl_xor_sync(0xffffffffu, sm, o);
    float inv = 1.f/sm;
    g_attn[(size_t)id*TKV + lane] = e1*inv;
    if (lane < TKV-32) g_attn[(size_t)id*TKV + 32 + lane] = e2*inv;
}

// ===================== ring gather + mix (fp32 + bf16 hi/lo) ======
__global__ void k_ring(const float* __restrict__ x) {
    __shared__ float xs[512*17];
    int b = blockIdx.z, l0 = blockIdx.y*16, nc = blockIdx.x;
    const float* xp = x + ((size_t)b*LL + l0)*NNV;
    for (int i = threadIdx.x; i < 16*512; i += 256) {
        int l = i >> 9, n = i & 511;
        xs[n*17 + l] = xp[(size_t)l*NNV + n];
    }
    __syncthreads();
    int n = nc*256 + threadIdx.x;
    float acc[16];
#pragma unroll
    for (int l = 0; l < 16; l++) acc[l] = 0.f;
    size_t abase = ((size_t)b*512 + n)*TKV;
    int ibase = n*TKV;
    for (int k = 0; k < TKV; k++) {
        float a = g_attn[abase + k];
        int m = g_topk[ibase + k];
        const float* xm = &xs[m*17];
#pragma unroll
        for (int l = 0; l < 16; l++) acc[l] += a*xm[l];
    }
    float imp = g_imp[b*512 + n];
    float omi = 1.f - imp;
    const float* xn = &xs[n*17];
#pragma unroll
    for (int l = 0; l < 16; l++) {
        size_t row = (size_t)b*LL + l0 + l;
        float v = imp*acc[l] + omi*xn[l];
        g_ring[row*NNV + n] = v;
        __nv_bfloat16 h, lo;
        bfsplit(v, h, lo);
        g_A1h[row*KE2 + n] = h;
        g_A1l[row*KE2 + n] = lo;
    }
}

// ===================== cluster weights =====================
__global__ void k_cw(const float* __restrict__ cluster_score) {
    int n = blockIdx.x*256 + threadIdx.x;
    if (n >= NNV) return;
    float v[16], mx = -3e38f;
#pragma unroll
    for (int c = 0; c < 16; c++) { v[c] = cluster_score[n*16+c]; mx = fmaxf(mx, v[c]); }
    float s = 0.f;
#pragma unroll
    for (int c = 0; c < 16; c++) { v[c] = expf(v[c]-mx); s += v[c]; }
    float inv = 1.f/s;
#pragma unroll
    for (int c = 0; c < 16; c++) {
        float e = v[c]*inv;
        g_cw[n*16+c] = e;
        g_cwT[c*512+n] = e;
    }
}

__global__ void k_prep(const float* __restrict__ varproj_w, const float* __restrict__ varproj_b,
                       const float* __restrict__ cp1_w, const float* __restrict__ cp1_b,
                       const float* __restrict__ cp2_w, const float* __restrict__ cp2_b) {
    int tid = threadIdx.x;
    for (int id = tid; id < 1024; id += 256) {
        int c = id >> 6, e = id & 63;
        float s = 0.f;
        for (int d = 0; d < 64; d++) s += varproj_w[c*64+d]*cp1_w[d*64+e];
        g_M1[id] = s;
    }
    if (tid < 64) {
        int e = tid;
        float bbv = cp1_b[e];
        for (int d = 0; d < 64; d++) bbv += varproj_b[d]*cp1_w[d*64+e];
        g_bb[e] = bbv;
        float w2 = 0.f;
        for (int d = 0; d < 64; d++) w2 += cp2_w[e*64+d];
        g_w2[e] = w2;
    }
    if (tid == 0) {
        float s = 0.f;
        for (int d = 0; d < 64; d++) s += cp2_b[d];
        g_b2s = s;
    }
}

// ===== weight transpose + bf16 split + rank-16 fold (G2 = cwT @ Wr) =====
__global__ void k_prepw(const float* __restrict__ Wd, const float* __restrict__ Wr,
                        __nv_bfloat16* __restrict__ oh, __nv_bfloat16* __restrict__ ol) {
    __shared__ float colv[512];
    int n = blockIdx.x;
    int tid = threadIdx.x;   // 128 threads
    for (int k = tid; k < 512; k += 128) {
        float w = Wd[(size_t)k*512 + n];
        __nv_bfloat16 h, l;
        bfsplit(w, h, l);
        oh[(size_t)n*KE2 + k] = h;
        ol[(size_t)n*KE2 + k] = l;
    }
    for (int m = tid; m < 512; m += 128) colv[m] = Wr[(size_t)m*512 + n];
    __syncthreads();
    if (tid < 16) {
        float s = 0.f;
        for (int m = 0; m < 512; m++) s += g_cwT[tid*512 + m]*colv[m];
        __nv_bfloat16 h, l;
        bfsplit(s, h, l);
        oh[(size_t)n*KE2 + 512 + tid] = h;
        ol[(size_t)n*KE2 + 512 + tid] = l;
    } else if (tid < 32) {
        __nv_bfloat16 z = __float2bfloat16(0.f);
        oh[(size_t)n*KE2 + 512 + tid] = z;
        ol[(size_t)n*KE2 + 512 + tid] = z;
    }
}

// ===================== center tokens + projection =====================
__global__ void k_ct(const float* __restrict__ cg_w, const float* __restrict__ cg_b) {
    int b = blockIdx.x;
    int j = blockIdx.y*256 + threadIdx.x;
    float s = cg_b[j];
    for (int n = 0; n < NNV; n++) s += g_summary[b*512+n]*cg_w[(size_t)n*1024 + j];
    g_ct[b*1024 + j] = s;
}

__global__ void k_ctp(const float* __restrict__ cp1_w) {
    int id = blockIdx.x*256 + threadIdx.x;
    if (id >= BB*16*64) return;
    int b = id >> 10;
    int cd = id & 1023;
    int c = cd >> 6, e = cd & 63;
    float s = 0.f;
    for (int d = 0; d < 64; d++) s += g_ct[b*1024 + c*64 + d]*cp1_w[d*64+e];
    g_ctp[id] = s;
}

// ===================== xcs = x @ cw =====================
__global__ void k_xcs(const float* __restrict__ x) {
    __shared__ float xs[16*512];
    int row0 = blockIdx.x*16;
    const float* xp = x + (size_t)row0*NNV;
    for (int i = threadIdx.x; i < 16*512; i += 256) xs[i] = xp[i];
    __syncthreads();
    int l = threadIdx.x >> 4, c = threadIdx.x & 15;
    float s = 0.f;
    for (int n = 0; n < NNV; n++) s += xs[l*512+n]*__ldg(&g_cw[n*16+c]);
    g_xcs[(size_t)(row0+l)*16 + c] = s;
}

// ========== Sc (gelu-folded) + c2v + Sc K-extension columns ==========
__global__ void k_scc2v() {
    __shared__ float sxc[16], sx[64], red[128], sSc[16];
    size_t bl = blockIdx.x;
    int b = (int)(bl >> 11);
    int tid = threadIdx.x;
    if (tid < 16) sxc[tid] = g_xcs[bl*16 + tid];
    __syncthreads();
    if (tid < 64) {
        float s = g_bb[tid];
#pragma unroll
        for (int c = 0; c < 16; c++) s += sxc[c]*g_M1[c*64 + tid];
        sx[tid] = s;
    }
    __syncthreads();
    int c = tid >> 3, gi = tid & 7;
    float p = 0.f;
    const float* ctp = &g_ctp[(size_t)b*1024 + c*64];
#pragma unroll
    for (int ee = 0; ee < 8; ee++) {
        int e = gi*8 + ee;
        float t = sx[e] + ctp[e];
        p += (0.5f*t*(1.f + erff(t*0.70710678118654752f)))*g_w2[e];
    }
    red[tid] = p;
    __syncthreads();
    if (tid < 16) {
        float s = g_b2s;
#pragma unroll
        for (int gg = 0; gg < 8; gg++) s += red[tid*8 + gg];
        sSc[tid] = s;
    }
    __syncthreads();
    if (tid < 16) {
        float v = sSc[tid];
        __nv_bfloat16 h, l;
        bfsplit(v, h, l);
        size_t o = bl*KE2 + 512 + tid;
        g_A1h[o] = h; g_A1l[o] = l;
        g_A2h[o] = h; g_A2l[o] = l;
    } else if (tid < 32) {
        __nv_bfloat16 z = __float2bfloat16(0.f);
        size_t o = bl*KE2 + 512 + tid;
        g_A1h[o] = z; g_A1l[o] = z;
        g_A2h[o] = z; g_A2l[o] = z;
    }
    float sc[16];
#pragma unroll
    for (int cc = 0; cc < 16; cc++) sc[cc] = sSc[cc];
    float* op = &g_c2v[bl*NNV];
    for (int n = tid; n < NNV; n += 128) {
        float a = 0.f;
#pragma unroll
        for (int cc = 0; cc < 16; cc++) a += sc[cc]*__ldg(&g_cwT[cc*512 + n]);
        op[n] = a;
    }
}

// ===================== layernorm =====================
__global__ void k_ln(const float* __restrict__ lng, const float* __restrict__ lnb,
                     float* __restrict__ out) {
    __shared__ float ss[4], sq[4];
    int row = blockIdx.x, tid = threadIdx.x;
    float4 h4 = ((const float4*)(g_h + (size_t)row*NNV))[tid];
    float s = h4.x + h4.y + h4.z + h4.w;
    float q = h4.x*h4.x + h4.y*h4.y + h4.z*h4.z + h4.w*h4.w;
#pragma unroll
    for (int o = 16; o; o >>= 1) {
        s += __shfl_xor_sync(0xffffffffu, s, o);
        q += __shfl_xor_sync(0xffffffffu, q, o);
    }
    if ((tid & 31) == 0) { ss[tid>>5] = s; sq[tid>>5] = q; }
    __syncthreads();
    s = ss[0] + ss[1] + ss[2] + ss[3];
    q = sq[0] + sq[1] + sq[2] + sq[3];
    float mu = s*(1.f/NNV);
    float var = q*(1.f/NNV) - mu*mu;
    float inv = rsqrtf(var + 1e-5f);
    float4 g4 = ((const float4*)lng)[tid];
    float4 b4 = ((const float4*)lnb)[tid];
    float4 o4;
    o4.x = (h4.x - mu)*inv*g4.x + b4.x;
    o4.y = (h4.y - mu)*inv*g4.y + b4.y;
    o4.z = (h4.z - mu)*inv*g4.z + b4.z;
    o4.w = (h4.w - mu)*inv*g4.w + b4.w;
    ((float4*)(out + (size_t)row*NNV))[tid] = o4;
}

// ===================== launch =====================
extern "C" void kernel_launch(void* const* d_in, const int* in_sizes, int n_in,
                              void* d_out, int out_size) {
    const float* x          = (const float*)d_in[0];
    const float* var_embed  = (const float*)d_in[1];
    const float* temp_w     = (const float*)d_in[2];
    const float* temp_b     = (const float*)d_in[3];
    const float* q_w        = (const float*)d_in[4];
    const float* q_b        = (const float*)d_in[5];
    const float* k_w        = (const float*)d_in[6];
    const float* k_b        = (const float*)d_in[7];
    const float* imp_w      = (const float*)d_in[8];
    const float* imp_b      = (const float*)d_in[9];
    const float* cluster_sc = (const float*)d_in[10];
    const float* varproj_w  = (const float*)d_in[11];
    const float* varproj_b  = (const float*)d_in[12];
    const float* cp1_w      = (const float*)d_in[13];
    const float* cp1_b      = (const float*)d_in[14];
    const float* cp2_w      = (const float*)d_in[15];
    const float* cp2_b      = (const float*)d_in[16];
    const float* cg_w       = (const float*)d_in[17];
    const float* cg_b       = (const float*)d_in[18];
    const float* gate_w     = (const float*)d_in[19];
    const float* gate_b     = (const float*)d_in[20];
    const float* fus_w      = (const float*)d_in[21];
    const float* fus_b      = (const float*)d_in[22];
    const float* ln_g       = (const float*)d_in[23];
    const float* ln_b       = (const float*)d_in[24];
    float* out = (float*)d_out;

    float *p_ring, *p_c2v, *p_h, *p_simpart;
    __nv_bfloat16 *pA1h, *pA1l, *pA2h, *pA2l, *pB1h, *pB1l, *pB2h, *pB2l, *pnTh, *pnTl;
    cudaGetSymbolAddress((void**)&p_ring, g_ring);
    cudaGetSymbolAddress((void**)&p_c2v,  g_c2v);
    cudaGetSymbolAddress((void**)&p_h,    g_h);
    cudaGetSymbolAddress((void**)&p_simpart, g_simpart);
    cudaGetSymbolAddress((void**)&pA1h, g_A1h);
    cudaGetSymbolAddress((void**)&pA1l, g_A1l);
    cudaGetSymbolAddress((void**)&pA2h, g_A2h);
    cudaGetSymbolAddress((void**)&pA2l, g_A2l);
    cudaGetSymbolAddress((void**)&pB1h, g_B1h);
    cudaGetSymbolAddress((void**)&pB1l, g_B1l);
    cudaGetSymbolAddress((void**)&pB2h, g_B2h);
    cudaGetSymbolAddress((void**)&pB2l, g_B2l);
    cudaGetSymbolAddress((void**)&pnTh, g_nTh);
    cudaGetSymbolAddress((void**)&pnTl, g_nTl);

    const int GSMEM = 2 * BUFSTRIDE * 2;   // 81920 bytes
    cudaFuncSetAttribute(k_gmma<0>, cudaFuncAttributeMaxDynamicSharedMemorySize, GSMEM);
    cudaFuncSetAttribute(k_gmma<1>, cudaFuncAttributeMaxDynamicSharedMemorySize, GSMEM);
    cudaFuncSetAttribute(k_gmma<2>, cudaFuncAttributeMaxDynamicSharedMemorySize, GSMEM);

    // 0-3: mask prep; index 3 = tensor GEMM (profiled slot)
    k_colstats<<<(LL*NNV+255)/256, 256>>>(x);
    k_cw<<<2, 256>>>(cluster_sc);
    k_prep<<<1, 256>>>(varproj_w, varproj_b, cp1_w, cp1_b, cp2_w, cp2_b);
    k_gmma<0><<<dim3(4,4,8), 256, GSMEM>>>(pnTh, pnTl, LL, pnTh, pnTl, LL,
                                           256, 8, nullptr, nullptr, nullptr,
                                           nullptr, nullptr, p_simpart);
    k_simred<<<NNV*NNV/256, 256>>>();
    k_topk<<<NNV/4, 128>>>();

    // router path
    k_partsums<<<BB*16, 256>>>(x);
    k_router<<<BB*NNV/256, 256>>>(var_embed, temp_w, temp_b, q_w, q_b, k_w, k_b, imp_w, imp_b);
    k_attn<<<BB*NNV/8, 256>>>();
    k_prepw<<<512, 128>>>(gate_w, gate_w + 512*512, pB1h, pB1l);
    k_prepw<<<512, 128>>>(fus_w, fus_w, pB2h, pB2l);
    k_ring<<<dim3(2, LL/16, BB), 256>>>(x);

    // center path
    k_ct<<<dim3(BB, 4), 256>>>(cg_w, cg_b);
    k_ctp<<<BB*16*64/256, 256>>>(cp1_w);
    k_xcs<<<BLV/16, 256>>>(x);
    k_scc2v<<<BLV, 128>>>();

    // tensor-core GEMMs (gate, fuse) + LN
    k_gmma<1><<<dim3(4, BLV/128), 256, GSMEM>>>(pA1h, pA1l, KE2, pB1h, pB1l, KE2,
                                                0, 17, gate_b, p_ring, p_c2v,
                                                pA2h, pA2l, nullptr);
    k_gmma<2><<<dim3(4, BLV/128), 256, GSMEM>>>(pA2h, pA2l, KE2, pB2h, pB2l, KE2,
                                                0, 17, fus_b, x, nullptr,
                                                nullptr, nullptr, p_h);
    k_ln<<<BLV, 128>>>(ln_g, ln_b, out);

    (void)in_sizes; (void)n_in; (void)out_size;
}